// round 8
// baseline (speedup 1.0000x reference)
#include <cuda_runtime.h>
#include <cstdint>

// Problem constants
#define Bn      32
#define Tn      24
#define Sn      768
#define SPLIT   4                // CTAs per cluster (per batch)
#define KT      (Sn / SPLIT)     // 192 output columns per CTA
#define CT      3                // column tiles of 64 floats per CTA
#define STR     8                // row stripes
#define NW      (CT * STR)       // 24 warps
#define NTHR    (NW * 32)        // 768 threads
#define RSTRIDE (2 * STR)        // 16 rows between a thread's iterations
#define NJ      (Sn / RSTRIDE)   // 48 iterations / thread / step (12 groups of 4)

__device__ __forceinline__ uint32_t smem_u32(const void* p) {
    return (uint32_t)__cvta_generic_to_shared(p);
}

__global__ void __cluster_dims__(SPLIT, 1, 1) __launch_bounds__(NTHR, 1)
scan_matvec_kernel(const float* __restrict__ inp,
                   const float* __restrict__ param,
                   float* __restrict__ out)
{
    __shared__ float  ybuf[2][Sn];       // double-buffered y for this batch
    __shared__ float4 red[STR][KT / 4];  // [8][48] stripe partials

    const int tid  = threadIdx.x;
    const int w    = tid >> 5;
    const int lane = tid & 31;
    const int c    = w % CT;        // column tile (64 floats)
    const int s    = w / CT;        // row stripe
    const int half = lane >> 4;     // row within pair
    const int g    = lane & 15;     // float4 group within tile
    const int b    = blockIdx.x / SPLIT;

    uint32_t rank;
    asm("mov.u32 %0, %%cluster_ctarank;" : "=r"(rank));
    const int k0 = (int)rank * KT;
    const int i0 = 2 * s + half;

    // lanes 0-15: 256B of row i0, lanes 16-31: 256B of row i0+1 -> 4 lines/LDG
    const float* Mth = inp + (size_t)b * Tn * Sn * Sn
                           + (size_t)i0 * Sn + (k0 + c * 64 + g * 4);

    // y0 = param + 1
    ybuf[0][tid] = param[tid] + 1.0f;

    // prologue: prefetch group 0 of step 0 (independent of y)
    float4 mA0, mA1, mA2, mA3, mB0, mB1, mB2, mB3;
    mA0 = __ldcs((const float4*)(Mth + (size_t)0 * RSTRIDE * Sn));
    mA1 = __ldcs((const float4*)(Mth + (size_t)1 * RSTRIDE * Sn));
    mA2 = __ldcs((const float4*)(Mth + (size_t)2 * RSTRIDE * Sn));
    mA3 = __ldcs((const float4*)(Mth + (size_t)3 * RSTRIDE * Sn));

    __syncthreads();

    int p = 0;
    for (int t = 0; t < Tn; ++t) {
        const float* mp = Mth + (size_t)t * Sn * Sn;
        // prefetch target for the cross-step group (dummy self-reload on last step)
        const float* nx = (t < Tn - 1) ? mp + (size_t)Sn * Sn : mp;
        const float* yp = ybuf[p];

        float ax = 0.f, ay = 0.f, az = 0.f, aw = 0.f;

        #pragma unroll
        for (int q = 0; q < 6; ++q) {
            const int jA = 8 * q;       // group resident in mA
            const int jB = 8 * q + 4;   // group to load into mB

            // load mB (current step)
            mB0 = __ldcs((const float4*)(mp + (size_t)(jB + 0) * RSTRIDE * Sn));
            mB1 = __ldcs((const float4*)(mp + (size_t)(jB + 1) * RSTRIDE * Sn));
            mB2 = __ldcs((const float4*)(mp + (size_t)(jB + 2) * RSTRIDE * Sn));
            mB3 = __ldcs((const float4*)(mp + (size_t)(jB + 3) * RSTRIDE * Sn));

            // FMA mA
            {
                float y0 = yp[i0 + (jA + 0) * RSTRIDE];
                float y1 = yp[i0 + (jA + 1) * RSTRIDE];
                float y2 = yp[i0 + (jA + 2) * RSTRIDE];
                float y3 = yp[i0 + (jA + 3) * RSTRIDE];
                ax = fmaf(y0, mA0.x, ax); ay = fmaf(y0, mA0.y, ay);
                az = fmaf(y0, mA0.z, az); aw = fmaf(y0, mA0.w, aw);
                ax = fmaf(y1, mA1.x, ax); ay = fmaf(y1, mA1.y, ay);
                az = fmaf(y1, mA1.z, az); aw = fmaf(y1, mA1.w, aw);
                ax = fmaf(y2, mA2.x, ax); ay = fmaf(y2, mA2.y, ay);
                az = fmaf(y2, mA2.z, az); aw = fmaf(y2, mA2.w, aw);
                ax = fmaf(y3, mA3.x, ax); ay = fmaf(y3, mA3.y, ay);
                az = fmaf(y3, mA3.z, az); aw = fmaf(y3, mA3.w, aw);
            }

            // load mA: next group of this step, or group 0 of step t+1 at q==5.
            // The q==5 loads are issued BEFORE the reduce/cluster-sync below,
            // so their DRAM latency hides under the barrier.
            {
                const float* pn = (q < 5) ? mp : nx;
                const int    jN = (q < 5) ? (8 * q + 8) : 0;
                mA0 = __ldcs((const float4*)(pn + (size_t)(jN + 0) * RSTRIDE * Sn));
                mA1 = __ldcs((const float4*)(pn + (size_t)(jN + 1) * RSTRIDE * Sn));
                mA2 = __ldcs((const float4*)(pn + (size_t)(jN + 2) * RSTRIDE * Sn));
                mA3 = __ldcs((const float4*)(pn + (size_t)(jN + 3) * RSTRIDE * Sn));
            }

            // FMA mB
            {
                float y0 = yp[i0 + (jB + 0) * RSTRIDE];
                float y1 = yp[i0 + (jB + 1) * RSTRIDE];
                float y2 = yp[i0 + (jB + 2) * RSTRIDE];
                float y3 = yp[i0 + (jB + 3) * RSTRIDE];
                ax = fmaf(y0, mB0.x, ax); ay = fmaf(y0, mB0.y, ay);
                az = fmaf(y0, mB0.z, az); aw = fmaf(y0, mB0.w, aw);
                ax = fmaf(y1, mB1.x, ax); ay = fmaf(y1, mB1.y, ay);
                az = fmaf(y1, mB1.z, az); aw = fmaf(y1, mB1.w, aw);
                ax = fmaf(y2, mB2.x, ax); ay = fmaf(y2, mB2.y, ay);
                az = fmaf(y2, mB2.z, az); aw = fmaf(y2, mB2.w, aw);
                ax = fmaf(y3, mB3.x, ax); ay = fmaf(y3, mB3.y, ay);
                az = fmaf(y3, mB3.z, az); aw = fmaf(y3, mB3.w, aw);
            }
        }

        // combine the two row-halves (same columns) within the warp
        ax += __shfl_down_sync(0xffffffffu, ax, 16);
        ay += __shfl_down_sync(0xffffffffu, ay, 16);
        az += __shfl_down_sync(0xffffffffu, az, 16);
        aw += __shfl_down_sync(0xffffffffu, aw, 16);

        if (half == 0)
            red[s][c * 16 + g] = make_float4(ax, ay, az, aw);
        __syncthreads();

        // 48 threads: reduce 8 stripes, then relu + cluster broadcast
        if (tid < KT / 4) {
            float4 r = red[0][tid];
            #pragma unroll
            for (int ss = 1; ss < STR; ++ss) {
                float4 q4 = red[ss][tid];
                r.x += q4.x; r.y += q4.y; r.z += q4.z; r.w += q4.w;
            }
            if (t == Tn - 1) {
                // final step: PRE-ReLU y
                *reinterpret_cast<float4*>(out + (size_t)b * Sn + k0 + tid * 4) = r;
            } else {
                r.x = fmaxf(r.x, 0.f); r.y = fmaxf(r.y, 0.f);
                r.z = fmaxf(r.z, 0.f); r.w = fmaxf(r.w, 0.f);
                uint32_t la = smem_u32(&ybuf[p ^ 1][k0 + tid * 4]);
                #pragma unroll
                for (int rr = 0; rr < SPLIT; ++rr) {
                    uint32_t ra;
                    asm("mapa.shared::cluster.u32 %0, %1, %2;"
                        : "=r"(ra) : "r"(la), "r"(rr));
                    asm volatile("st.shared::cluster.v4.f32 [%0], {%1,%2,%3,%4};"
                                 :: "r"(ra), "f"(r.x), "f"(r.y), "f"(r.z), "f"(r.w)
                                 : "memory");
                }
            }
        }

        if (t < Tn - 1) {
            // one cluster barrier per step: release DSMEM y stores,
            // acquire before anyone reads ybuf[p^1]. The q==5 prefetch
            // loads are in flight across this barrier.
            asm volatile("barrier.cluster.arrive.aligned;" ::: "memory");
            asm volatile("barrier.cluster.wait.aligned;"   ::: "memory");
            p ^= 1;
        }
    }
}

extern "C" void kernel_launch(void* const* d_in, const int* in_sizes, int n_in,
                              void* d_out, int out_size)
{
    const float* inp   = (const float*)d_in[0];   // [32, 24, 768, 768] f32
    const float* param = (const float*)d_in[1];   // [768] f32
    float* out = (float*)d_out;                   // [32, 768] f32

    (void)in_sizes; (void)n_in; (void)out_size;

    scan_matvec_kernel<<<Bn * SPLIT, NTHR>>>(inp, param, out);
}

// round 9
// speedup vs baseline: 1.4569x; 1.4569x over previous
#include <cuda_runtime.h>
#include <cstdint>

// Problem constants
#define Bn      32
#define Tn      24
#define Sn      768
#define SPLIT   4                // CTAs per cluster (per batch)
#define KT      (Sn / SPLIT)     // 192 output columns per CTA
#define CT      3                // column tiles of 64 floats per CTA
#define STR     8                // row stripes
#define NW      (CT * STR)       // 24 warps
#define NTHR    (NW * 32)        // 768 threads

__device__ __forceinline__ uint32_t smem_u32(const void* p) {
    return (uint32_t)__cvta_generic_to_shared(p);
}

__global__ void __cluster_dims__(SPLIT, 1, 1) __launch_bounds__(NTHR, 1)
scan_matvec_kernel(const float* __restrict__ inp,
                   const float* __restrict__ param,
                   float* __restrict__ out)
{
    __shared__ float  ybuf[2][Sn];       // double-buffered y for this batch
    __shared__ float4 red[STR][KT / 4];  // [8][48] stripe partials
    __shared__ float  lyc[Sn];           // compacted nonzero y values
    __shared__ int    lidx[Sn];          // compacted nonzero row indices
    __shared__ int    wsum[NW], wpre[NW];
    __shared__ int    s_nnz, s_nnzPad;

    const int tid  = threadIdx.x;
    const int w    = tid >> 5;
    const int lane = tid & 31;
    const int c    = w % CT;        // column tile (64 floats)
    const int s    = w / CT;        // row stripe
    const int half = lane >> 4;     // row within pair
    const int g    = lane & 15;     // float4 group within tile
    const int b    = blockIdx.x / SPLIT;
    const int tpos = 2 * s + half;  // this thread's slot within a 16-row pack

    uint32_t rank;
    asm("mov.u32 %0, %%cluster_ctarank;" : "=r"(rank));
    const int k0     = (int)rank * KT;
    const int colOff = k0 + c * 64 + g * 4;

    // y0 = param + 1 (no relu on the initial vector)
    ybuf[0][tid] = param[tid] + 1.0f;

    // cluster handshake before any DSMEM traffic later
    asm volatile("barrier.cluster.arrive.aligned;" ::: "memory");
    asm volatile("barrier.cluster.wait.aligned;"   ::: "memory");

    int p = 0;
    for (int t = 0; t < Tn; ++t) {
        // ---- compact nonzeros of ybuf[p] into (lidx, lyc), pad to mult of 64 ----
        {
            float v = ybuf[p][tid];            // own element (self-written or post-sync)
            bool nz = (v != 0.0f);
            unsigned m = __ballot_sync(0xffffffffu, nz);
            if (lane == 0) wsum[w] = __popc(m);
            __syncthreads();
            if (tid < 32) {
                int val = (tid < NW) ? wsum[tid] : 0;
                #pragma unroll
                for (int d = 1; d < 32; d <<= 1) {
                    int n = __shfl_up_sync(0xffffffffu, val, d);
                    if (lane >= d) val += n;
                }
                if (tid < NW) wpre[tid] = val;            // inclusive scan
                if (tid == NW - 1) {
                    s_nnz    = val;
                    s_nnzPad = (val + 63) & ~63;
                }
            }
            __syncthreads();
            int off = (w ? wpre[w - 1] : 0) + __popc(m & ((1u << lane) - 1));
            if (nz) { lyc[off] = v; lidx[off] = tid; }
            int nnz = s_nnz, nnzPad = s_nnzPad;
            if (nnz + tid < nnzPad) { lyc[nnz + tid] = 0.0f; lidx[nnz + tid] = 0; }
            __syncthreads();
        }
        const int Gq = s_nnzPad >> 6;   // groups of 64 list entries

        // ---- matvec over the compacted row list ----
        const float* Mt = inp + ((size_t)b * Tn + t) * Sn * Sn + colOff;

        float ax = 0.f, ay = 0.f, az = 0.f, aw = 0.f;
        float4 MA[4], MB[4];
        float  YA[4], YB[4];

        auto ldgrp = [&](int grp, float4 mreg[4], float yreg[4]) {
            #pragma unroll
            for (int u = 0; u < 4; ++u) {
                int pos = grp * 64 + u * 16 + tpos;
                int r   = lidx[pos];
                yreg[u] = lyc[pos];
                mreg[u] = __ldcs(reinterpret_cast<const float4*>(Mt + (size_t)r * Sn));
            }
        };

        if (Gq > 0) ldgrp(0, MA, YA);
        if (Gq > 1) ldgrp(1, MB, YB);

        for (int q = 0; q < Gq; ++q) {
            if ((q & 1) == 0) {
                #pragma unroll
                for (int u = 0; u < 4; ++u) {
                    ax = fmaf(YA[u], MA[u].x, ax); ay = fmaf(YA[u], MA[u].y, ay);
                    az = fmaf(YA[u], MA[u].z, az); aw = fmaf(YA[u], MA[u].w, aw);
                }
                if (q + 2 < Gq) ldgrp(q + 2, MA, YA);
            } else {
                #pragma unroll
                for (int u = 0; u < 4; ++u) {
                    ax = fmaf(YB[u], MB[u].x, ax); ay = fmaf(YB[u], MB[u].y, ay);
                    az = fmaf(YB[u], MB[u].z, az); aw = fmaf(YB[u], MB[u].w, aw);
                }
                if (q + 2 < Gq) ldgrp(q + 2, MB, YB);
            }
        }

        // combine the two row-halves (same columns) within the warp
        ax += __shfl_down_sync(0xffffffffu, ax, 16);
        ay += __shfl_down_sync(0xffffffffu, ay, 16);
        az += __shfl_down_sync(0xffffffffu, az, 16);
        aw += __shfl_down_sync(0xffffffffu, aw, 16);

        if (half == 0)
            red[s][c * 16 + g] = make_float4(ax, ay, az, aw);
        __syncthreads();

        // 48 threads: reduce 8 stripes, then relu + cluster broadcast
        if (tid < KT / 4) {
            float4 r = red[0][tid];
            #pragma unroll
            for (int ss = 1; ss < STR; ++ss) {
                float4 q4 = red[ss][tid];
                r.x += q4.x; r.y += q4.y; r.z += q4.z; r.w += q4.w;
            }
            if (t == Tn - 1) {
                // final step: PRE-ReLU y
                *reinterpret_cast<float4*>(out + (size_t)b * Sn + k0 + tid * 4) = r;
            } else {
                r.x = fmaxf(r.x, 0.f); r.y = fmaxf(r.y, 0.f);
                r.z = fmaxf(r.z, 0.f); r.w = fmaxf(r.w, 0.f);
                uint32_t la = smem_u32(&ybuf[p ^ 1][k0 + tid * 4]);
                #pragma unroll
                for (int rr = 0; rr < SPLIT; ++rr) {
                    uint32_t ra;
                    asm("mapa.shared::cluster.u32 %0, %1, %2;"
                        : "=r"(ra) : "r"(la), "r"(rr));
                    asm volatile("st.shared::cluster.v4.f32 [%0], {%1,%2,%3,%4};"
                                 :: "r"(ra), "f"(r.x), "f"(r.y), "f"(r.z), "f"(r.w)
                                 : "memory");
                }
            }
        }

        if (t < Tn - 1) {
            // one cluster barrier per step: release DSMEM y stores,
            // acquire before the next compaction reads ybuf[p^1]
            asm volatile("barrier.cluster.arrive.aligned;" ::: "memory");
            asm volatile("barrier.cluster.wait.aligned;"   ::: "memory");
            p ^= 1;
        }
    }
}

extern "C" void kernel_launch(void* const* d_in, const int* in_sizes, int n_in,
                              void* d_out, int out_size)
{
    const float* inp   = (const float*)d_in[0];   // [32, 24, 768, 768] f32
    const float* param = (const float*)d_in[1];   // [768] f32
    float* out = (float*)d_out;                   // [32, 768] f32

    (void)in_sizes; (void)n_in; (void)out_size;

    scan_matvec_kernel<<<Bn * SPLIT, NTHR>>>(inp, param, out);
}

// round 10
// speedup vs baseline: 1.5426x; 1.0588x over previous
#include <cuda_runtime.h>
#include <cstdint>

// Problem constants
#define Bn      32
#define Tn      24
#define Sn      768
#define SPLIT   4                // CTAs per cluster (per batch)
#define KT      (Sn / SPLIT)     // 192 output columns per CTA
#define CT      3                // column tiles of 64 floats per CTA
#define STR     8                // row stripes
#define NW      (CT * STR)       // 24 warps
#define NTHR    (NW * 32)        // 768 threads
#define RSTRIDE (2 * STR)        // 16 rows between a thread's iterations
#define JG      8                // front-batched loads per group
#define NG      (Sn / (RSTRIDE * JG))  // 6 groups per step

__device__ __forceinline__ uint32_t smem_u32(const void* p) {
    return (uint32_t)__cvta_generic_to_shared(p);
}

__global__ void __cluster_dims__(SPLIT, 1, 1) __launch_bounds__(NTHR, 1)
scan_matvec_kernel(const float* __restrict__ inp,
                   const float* __restrict__ param,
                   float* __restrict__ out)
{
    __shared__ float  ybuf[2][Sn];       // double-buffered y for this batch
    __shared__ float4 red[STR][KT / 4];  // [8][48] stripe partials

    const int tid  = threadIdx.x;
    const int w    = tid >> 5;
    const int lane = tid & 31;
    const int c    = w % CT;        // column tile (64 floats)
    const int s    = w / CT;        // row stripe
    const int half = lane >> 4;     // row within pair
    const int g    = lane & 15;     // float4 group within tile
    const int b    = blockIdx.x / SPLIT;

    uint32_t rank;
    asm("mov.u32 %0, %%cluster_ctarank;" : "=r"(rank));
    const int k0 = (int)rank * KT;
    const int i0 = 2 * s + half;

    // lanes 0-15: 256B of row i0, lanes 16-31: 256B of row i0+1 -> 4 lines/LDG
    const float* Mth = inp + (size_t)b * Tn * Sn * Sn
                           + (size_t)i0 * Sn + (k0 + c * 64 + g * 4);

    // y0 = param + 1 (dense; no zeros expected at t=0)
    ybuf[0][tid] = param[tid] + 1.0f;

    // cluster handshake before any DSMEM traffic later
    asm volatile("barrier.cluster.arrive.aligned;" ::: "memory");
    asm volatile("barrier.cluster.wait.aligned;"   ::: "memory");

    int p = 0;
    for (int t = 0; t < Tn; ++t) {
        const float* Mt = Mth + (size_t)t * Sn * Sn;   // thread's row i0, cols fixed
        const float* yp = ybuf[p];

        float ax = 0.f, ay = 0.f, az = 0.f, aw = 0.f;

        #pragma unroll
        for (int q = 0; q < NG; ++q) {
            float4 m[JG];
            float  yv[JG];
            // front-batched loads: 8 independent LDG.128 in flight.
            // Zero-y rows redirect to the thread's group-0 line (L1-hot),
            // saving the DRAM sectors; FMA with y=0 contributes nothing.
            #pragma unroll
            for (int u = 0; u < JG; ++u) {
                const int j = q * JG + u;
                yv[u] = yp[i0 + j * RSTRIDE];
                const float* pa = Mt + (size_t)j * RSTRIDE * Sn;
                pa = (yv[u] != 0.0f) ? pa : Mt;     // FSETP + SEL, branchless
                m[u] = __ldcs(reinterpret_cast<const float4*>(pa));
            }
            #pragma unroll
            for (int u = 0; u < JG; ++u) {
                ax = fmaf(yv[u], m[u].x, ax);
                ay = fmaf(yv[u], m[u].y, ay);
                az = fmaf(yv[u], m[u].z, az);
                aw = fmaf(yv[u], m[u].w, aw);
            }
        }

        // combine the two row-halves (same columns) within the warp
        ax += __shfl_down_sync(0xffffffffu, ax, 16);
        ay += __shfl_down_sync(0xffffffffu, ay, 16);
        az += __shfl_down_sync(0xffffffffu, az, 16);
        aw += __shfl_down_sync(0xffffffffu, aw, 16);

        if (half == 0)
            red[s][c * 16 + g] = make_float4(ax, ay, az, aw);
        __syncthreads();

        // 48 threads: reduce 8 stripes, then relu + cluster broadcast
        if (tid < KT / 4) {
            float4 r = red[0][tid];
            #pragma unroll
            for (int ss = 1; ss < STR; ++ss) {
                float4 q4 = red[ss][tid];
                r.x += q4.x; r.y += q4.y; r.z += q4.z; r.w += q4.w;
            }
            if (t == Tn - 1) {
                // final step: PRE-ReLU y
                *reinterpret_cast<float4*>(out + (size_t)b * Sn + k0 + tid * 4) = r;
            } else {
                r.x = fmaxf(r.x, 0.f); r.y = fmaxf(r.y, 0.f);
                r.z = fmaxf(r.z, 0.f); r.w = fmaxf(r.w, 0.f);
                uint32_t la = smem_u32(&ybuf[p ^ 1][k0 + tid * 4]);
                #pragma unroll
                for (int rr = 0; rr < SPLIT; ++rr) {
                    uint32_t ra;
                    asm("mapa.shared::cluster.u32 %0, %1, %2;"
                        : "=r"(ra) : "r"(la), "r"(rr));
                    asm volatile("st.shared::cluster.v4.f32 [%0], {%1,%2,%3,%4};"
                                 :: "r"(ra), "f"(r.x), "f"(r.y), "f"(r.z), "f"(r.w)
                                 : "memory");
                }
            }
        }

        if (t < Tn - 1) {
            // one cluster barrier per step: release DSMEM y stores,
            // acquire before anyone reads ybuf[p^1]
            asm volatile("barrier.cluster.arrive.aligned;" ::: "memory");
            asm volatile("barrier.cluster.wait.aligned;"   ::: "memory");
            p ^= 1;
        }
    }
}

extern "C" void kernel_launch(void* const* d_in, const int* in_sizes, int n_in,
                              void* d_out, int out_size)
{
    const float* inp   = (const float*)d_in[0];   // [32, 24, 768, 768] f32
    const float* param = (const float*)d_in[1];   // [768] f32
    float* out = (float*)d_out;                   // [32, 768] f32

    (void)in_sizes; (void)n_in; (void)out_size;

    scan_matvec_kernel<<<Bn * SPLIT, NTHR>>>(inp, param, out);
}

// round 13
// speedup vs baseline: 1.5575x; 1.0097x over previous
#include <cuda_runtime.h>
#include <cstdint>

// Problem constants
#define Bn      32
#define Tn      24
#define Sn      768
#define SPLIT   4                // CTAs per cluster (per batch)
#define KT      (Sn / SPLIT)     // 192 output columns per CTA
#define CT      3                // column tiles of 64 floats per CTA
#define STR     8                // row stripes
#define NW      (CT * STR)       // 24 warps
#define NTHR    (NW * 32)        // 768 threads
#define RSTRIDE (2 * STR)        // 16 rows between a thread's iterations
#define JG      8                // front-batched loads per group
#define NG      (Sn / (RSTRIDE * JG))  // 6 groups per step

__device__ __forceinline__ uint32_t smem_u32(const void* p) {
    return (uint32_t)__cvta_generic_to_shared(p);
}

__global__ void __cluster_dims__(SPLIT, 1, 1) __launch_bounds__(NTHR, 1)
scan_matvec_kernel(const float* __restrict__ inp,
                   const float* __restrict__ param,
                   float* __restrict__ out)
{
    __shared__ float  ybuf[2][Sn];       // double-buffered y for this batch
    __shared__ float4 red[STR][KT / 4];  // [8][48] stripe partials

    const int tid  = threadIdx.x;
    const int w    = tid >> 5;
    const int lane = tid & 31;
    const int c    = w % CT;        // column tile (64 floats)
    const int s    = w / CT;        // row stripe
    const int half = lane >> 4;     // row within pair
    const int g    = lane & 15;     // float4 group within tile
    const int b    = blockIdx.x / SPLIT;

    uint32_t rank;
    asm("mov.u32 %0, %%cluster_ctarank;" : "=r"(rank));
    const int k0 = (int)rank * KT;
    const int i0 = 2 * s + half;

    // lanes 0-15: 256B of row i0, lanes 16-31: 256B of row i0+1 -> 4 lines/LDG
    const float* Mth = inp + (size_t)b * Tn * Sn * Sn
                           + (size_t)i0 * Sn + (k0 + c * 64 + g * 4);

    // y0 = param + 1 (dense; no zeros expected at t=0)
    ybuf[0][tid] = param[tid] + 1.0f;

    // cluster handshake before any DSMEM traffic later
    asm volatile("barrier.cluster.arrive.aligned;" ::: "memory");
    asm volatile("barrier.cluster.wait.aligned;"   ::: "memory");

    int p = 0;
    for (int t = 0; t < Tn; ++t) {
        const float* Mt = Mth + (size_t)t * Sn * Sn;   // thread's row i0, cols fixed
        const float* yp = ybuf[p];

        float ax = 0.f, ay = 0.f, az = 0.f, aw = 0.f;

        #pragma unroll
        for (int q = 0; q < NG; ++q) {
            float4 m[JG];
            float  yv[JG];
            // front-batched loads: up to 8 independent LDG.128 in flight.
            // The skip predicate is uniform per half-warp, so @P LDG.128
            // either fetches its 2 lines or issues NOTHING — skipped rows
            // cost zero L1tex wavefronts and zero DRAM sectors.
            #pragma unroll
            for (int u = 0; u < JG; ++u) {
                const int j = q * JG + u;
                yv[u] = yp[i0 + j * RSTRIDE];
                float4 mv = make_float4(0.f, 0.f, 0.f, 0.f);
                if (yv[u] != 0.0f)
                    mv = __ldcs(reinterpret_cast<const float4*>(
                             Mt + (size_t)j * RSTRIDE * Sn));
                m[u] = mv;
            }
            #pragma unroll
            for (int u = 0; u < JG; ++u) {
                ax = fmaf(yv[u], m[u].x, ax);
                ay = fmaf(yv[u], m[u].y, ay);
                az = fmaf(yv[u], m[u].z, az);
                aw = fmaf(yv[u], m[u].w, aw);
            }
        }

        // combine the two row-halves (same columns) within the warp
        ax += __shfl_down_sync(0xffffffffu, ax, 16);
        ay += __shfl_down_sync(0xffffffffu, ay, 16);
        az += __shfl_down_sync(0xffffffffu, az, 16);
        aw += __shfl_down_sync(0xffffffffu, aw, 16);

        if (half == 0)
            red[s][c * 16 + g] = make_float4(ax, ay, az, aw);
        __syncthreads();

        // 48 threads: reduce 8 stripes, then relu + cluster broadcast
        if (tid < KT / 4) {
            float4 r = red[0][tid];
            #pragma unroll
            for (int ss = 1; ss < STR; ++ss) {
                float4 q4 = red[ss][tid];
                r.x += q4.x; r.y += q4.y; r.z += q4.z; r.w += q4.w;
            }
            if (t == Tn - 1) {
                // final step: PRE-ReLU y
                *reinterpret_cast<float4*>(out + (size_t)b * Sn + k0 + tid * 4) = r;
            } else {
                r.x = fmaxf(r.x, 0.f); r.y = fmaxf(r.y, 0.f);
                r.z = fmaxf(r.z, 0.f); r.w = fmaxf(r.w, 0.f);
                uint32_t la = smem_u32(&ybuf[p ^ 1][k0 + tid * 4]);
                #pragma unroll
                for (int rr = 0; rr < SPLIT; ++rr) {
                    uint32_t ra;
                    asm("mapa.shared::cluster.u32 %0, %1, %2;"
                        : "=r"(ra) : "r"(la), "r"(rr));
                    asm volatile("st.shared::cluster.v4.f32 [%0], {%1,%2,%3,%4};"
                                 :: "r"(ra), "f"(r.x), "f"(r.y), "f"(r.z), "f"(r.w)
                                 : "memory");
                }
            }
        }

        if (t < Tn - 1) {
            // one cluster barrier per step: release DSMEM y stores,
            // acquire before anyone reads ybuf[p^1]
            asm volatile("barrier.cluster.arrive.aligned;" ::: "memory");
            asm volatile("barrier.cluster.wait.aligned;"   ::: "memory");
            p ^= 1;
        }
    }
}

extern "C" void kernel_launch(void* const* d_in, const int* in_sizes, int n_in,
                              void* d_out, int out_size)
{
    const float* inp   = (const float*)d_in[0];   // [32, 24, 768, 768] f32
    const float* param = (const float*)d_in[1];   // [768] f32
    float* out = (float*)d_out;                   // [32, 768] f32

    (void)in_sizes; (void)n_in; (void)out_size;

    scan_matvec_kernel<<<Bn * SPLIT, NTHR>>>(inp, param, out);
}